// round 14
// baseline (speedup 1.0000x reference)
#include <cuda_runtime.h>
#include <math.h>

// ChfLoss: B=8, H=W=64, P=60. loss = (0.1/B) * sum_b ||CHF(dnn_b - gt_b)||_2
// Separable trig. ONE kernel, 120 blocks (1/SM), block-local trig table.
// R14: trig MUFU halved via r -> -r mirror symmetry; tail = one fixed-point
// RED per block + t0-only finalize (bar4/flag/broadcast deleted).

#define NB      8
#define HWD     64
#define PP      60
#define PTILES  15                  // 60 / 4 p-rows per block
#define NBLK    (NB * PTILES)       // 120
#define NT      256
#define FXSCALE 1048576.0           // 2^20 fixed-point scale

// __device__ globals = sanctioned scratch (no allocation allowed)
__device__ unsigned long long g_sum[NB] = {0};  // fixed-point per-batch sums
__device__ unsigned           g_count  = 0;     // completion counter (self-reset)

// Shared: D 4096 + CS 7680 + A 512 = 12288 floats = 48KB dynamic exactly.
// NO static __shared__ anywhere (would exceed the 48KB default limit).
__global__ __launch_bounds__(NT) void chf_fused_kernel(const float* __restrict__ dnn,
                                                       const float* __restrict__ gt,
                                                       float* __restrict__ out) {
    extern __shared__ float sm[];
    float*  sD  = sm;                               // [j*64 + i]
    float2* sCS = (float2*)(sm + 4096);             // [i*60 + q] (also [j*60 + p])
    float2* sA  = (float2*)(sm + 4096 + 7680);      // [i*4 + pl] = (Ac, As)

    const int blk = blockIdx.x;
    const int b   = blk / PTILES;
    const int pt  = blk - b * PTILES;
    const int p0  = pt * 4;
    const int t   = threadIdx.x;

    // ---- issue global loads FIRST (latency hidden by table gen below) ----
    const float4* d4 = (const float4*)(dnn + b * 4096);
    const float4* g4 = (const float4*)(gt  + b * 4096);
    float4 va[4], vg[4];
    #pragma unroll
    for (int k = 0; k < 4; k++) {                    // 4*256 = 1024 float4 = ALL of D
        va[k] = d4[t + k * NT];
        vg[k] = g4[t + k * NT];
    }

    // ---- trig table with mirror symmetry: sincos only for q=0 and q=30..59 ----
    // Ref: angle = fl(r_q * x_i) fp32, then cos/sin. r_{30-m} = -r_{30+m}
    // EXACTLY (IEEE sign symmetry), so angle mirrors sign-exactly:
    // (c,s)_{30-m} = (c, -s)_{30+m}. 31 sincos columns instead of 60.
    // Exact fp32 Cody-Waite: kk = rint(a/2pi) (|kk|<=243 exact);
    // fma(-kk, 6.28125f, a) EXACT; 2nd fma ~3e-7 rad; __sincosf ~5e-7 abs.
    {
        const float inv2pi = 0.15915494309189535f;
        const float C1 = 6.28125f;                   // 201/32, exact
        const float C2 = 1.9353071795864769e-3f;     // 2*pi - C1
        #pragma unroll
        for (int k = 0; k < 8; k++) {
            int e = t + k * NT;                      // 0..2047; valid < 64*31
            if (e < HWD * 31) {
                int i = e / 31;
                int m = e - i * 31;                  // 0..30
                int q = (m == 30) ? 0 : 30 + m;      // q=0 or 30..59
                float r  = (float)(q - 30) * 0.1f;   // fp32 grid, matches ref
                float x  = (float)(4 + 8 * i);       // linspace(4,508,64), exact
                float a  = r * x;                    // ref's fp32 angle
                float kk = rintf(a * inv2pi);
                float ar = fmaf(-kk, C1, a);         // exact
                ar       = fmaf(-kk, C2, ar);        // |ar| <= pi (+eps)
                float s, c;
                __sincosf(ar, &s, &c);
                sCS[i * 60 + q] = make_float2(c, s);
                if (m >= 1 && m <= 29)               // mirror q' = 30 - m
                    sCS[i * 60 + (30 - m)] = make_float2(c, -s);
            }
        }
    }

    // ---- D = dnn - gt into shared ----
    {
        float4* sD4 = (float4*)sD;
        #pragma unroll
        for (int k = 0; k < 4; k++) {
            sD4[t + k * NT] = make_float4(va[k].x - vg[k].x, va[k].y - vg[k].y,
                                          va[k].z - vg[k].z, va[k].w - vg[k].w);
        }
    }
    __syncthreads();                                 // bar 1: sD + sCS ready

    // ---- stage 1: t = pl*64 + ip*2 + jh -> 2 outputs (i = 2ip, 2ip+1) ----
    {
        const int jh = t & 1;                        // j half
        const int ip = (t >> 1) & 31;                // i pair
        const int pl = t >> 6;
        const int p  = p0 + pl;
        const int j0 = jh * 32;
        const float2* sD2 = (const float2*)sD;       // [j*32 + ip]
        float ac0 = 0.f, ac1 = 0.f, as0 = 0.f, as1 = 0.f;
        #pragma unroll 16
        for (int jj = 0; jj < 32; jj++) {
            int j = j0 + jj;
            float2 d  = sD2[j * 32 + ip];
            float2 cs = sCS[j * PP + p];             // broadcast (p uniform/warp)
            ac0 = fmaf(cs.x, d.x, ac0);
            ac1 = fmaf(cs.x, d.y, ac1);
            as0 = fmaf(cs.y, d.x, as0);
            as1 = fmaf(cs.y, d.y, as1);
        }
        // combine j halves with partner lane (t^1): exact & deterministic
        ac0 += __shfl_xor_sync(0xFFFFFFFFu, ac0, 1);
        ac1 += __shfl_xor_sync(0xFFFFFFFFu, ac1, 1);
        as0 += __shfl_xor_sync(0xFFFFFFFFu, as0, 1);
        as1 += __shfl_xor_sync(0xFFFFFFFFu, as1, 1);
        if (!jh) {
            sA[(2 * ip + 0) * 4 + pl] = make_float2(ac0, as0);
            sA[(2 * ip + 1) * 4 + pl] = make_float2(ac1, as1);
        }
    }
    __syncthreads();                                 // bar 2: sA ready

    // ---- stage 2: t<240: t = q2*8 + pl*2 + ih -> 2 outputs (q = 2q2, 2q2+1) ----
    float v = 0.f;
    {
        const int ih = t & 1;
        const int pl = (t >> 1) & 3;
        const int q2 = t >> 3;                       // 0..29 valid (t<240)
        float r0a = 0.f, r0b = 0.f, i0a = 0.f, i0b = 0.f;
        float r1a = 0.f, r1b = 0.f, i1a = 0.f, i1b = 0.f;
        if (q2 < 30) {
            const int istart = ih * 32;
            const float4* sCS4 = (const float4*)sCS; // [i*30 + q2] = q pair
            #pragma unroll 16
            for (int ii = 0; ii < 32; ii++) {
                int i = istart + ii;
                float2 a  = sA[i * 4 + pl];          // (Ac, As)
                float4 cs = sCS4[i * 30 + q2];       // (c_q0,s_q0,c_q1,s_q1)
                r0a = fmaf(a.x, cs.x, r0a);
                r0b = fmaf(a.y, cs.y, r0b);
                i0a = fmaf(a.y, cs.x, i0a);
                i0b = fmaf(a.x, cs.y, i0b);
                r1a = fmaf(a.x, cs.z, r1a);
                r1b = fmaf(a.y, cs.w, r1b);
                i1a = fmaf(a.y, cs.z, i1a);
                i1b = fmaf(a.x, cs.w, i1b);
            }
        }
        float re0 = r0a - r0b, im0 = i0a + i0b;
        float re1 = r1a - r1b, im1 = i1a + i1b;
        re0 += __shfl_xor_sync(0xFFFFFFFFu, re0, 1); // combine i halves (exact)
        im0 += __shfl_xor_sync(0xFFFFFFFFu, im0, 1);
        re1 += __shfl_xor_sync(0xFFFFFFFFu, re1, 1);
        im1 += __shfl_xor_sync(0xFFFFFFFFu, im1, 1);
        if (!ih && q2 < 30)
            v = fmaf(re0, re0, im0 * im0) + fmaf(re1, re1, im1 * im1);
    }

    // ---- block reduce: warp shfl -> sD partials (sD free since bar 2) ----
    #pragma unroll
    for (int off = 16; off > 0; off >>= 1)
        v += __shfl_down_sync(0xFFFFFFFFu, v, off);
    if ((t & 31) == 0) sD[t >> 5] = v;               // 8 warp partials
    __syncthreads();                                 // bar 3 (last barrier)

    // ---- t0: one fixed-point RED per block, counter; last block finalizes ----
    if (t == 0) {
        const float4* p4 = (const float4*)sD;        // 2x LDS.128
        float4 pa = p4[0], pb = p4[1];
        float s = ((pa.x + pa.y) + (pa.z + pa.w)) + ((pb.x + pb.y) + (pb.z + pb.w));
        // u64 fixed point: integer adds are order-free -> deterministic.
        // s <= ~1e8 -> fx <= ~1e14 << 2^64; quantization ~1e-10 rel.
        atomicAdd(&g_sum[b], (unsigned long long)((double)s * FXSCALE));
        __threadfence();                             // publish RED before counter
        unsigned c = atomicAdd(&g_count, 1u);
        if (c == NBLK - 1) {                         // last block: finalize alone
            g_count = 0;                             // reset for next graph replay
            __threadfence();                         // acquire: all REDs visible
            float w = 0.f;
            #pragma unroll
            for (int kk = 0; kk < NB; kk++) {
                unsigned long long fx =
                    *((volatile unsigned long long*)&g_sum[kk]);
                w += sqrtf((float)((double)fx * (1.0 / FXSCALE)));
                g_sum[kk] = 0ull;                    // reset for next replay
            }
            out[0] = w * 0.1f / 8.0f;
        }
    }
}

// ---------------------------------------------------------------------------
extern "C" void kernel_launch(void* const* d_in, const int* in_sizes, int n_in,
                              void* d_out, int out_size) {
    (void)in_sizes; (void)n_in; (void)out_size;
    const float* dnn = (const float*)d_in[0];
    const float* gt  = (const float*)d_in[1];
    float* out = (float*)d_out;

    chf_fused_kernel<<<NBLK, NT, 12288 * sizeof(float)>>>(dnn, gt, out);
}

// round 15
// speedup vs baseline: 1.4588x; 1.4588x over previous
#include <cuda_runtime.h>
#include <math.h>

// ChfLoss: B=8, H=W=64, P=60. loss = (0.1/B) * sum_b ||CHF(dnn_b - gt_b)||_2
// Separable trig + CONJUGATE SYMMETRY: r_{60-p} = -r_p exactly, so
// |M[60-p,60-q]|^2 == |M[p,q]|^2 bitwise (cos even / sin odd, termwise).
// Compute rows 0..30 only; double q>=1 points of rows 1..29; recover each
// missing (60-p, 0) point from conj(A[p]) via a sign flip. Half the
// contraction work of R13. ONE kernel, 128 blocks (1/SM).

#define NB      8
#define HWD     64
#define PP      60
#define BPB     16                  // blocks per batch (rows 0..30, 2 per block)
#define NBLK    (NB * BPB)          // 128
#define NT      256

// __device__ globals = sanctioned scratch (no allocation allowed)
__device__ float    g_part[NB * 16];      // [b*16 + bt], all 16 slots written
__device__ unsigned g_count = 0;          // completion counter (self-reset)

// Shared: D 4096 + CS 7680 + A 256 (+pad) = 12288 floats = 48KB dynamic.
// NO static __shared__ anywhere (would exceed the 48KB default limit).
__global__ __launch_bounds__(NT) void chf_fused_kernel(const float* __restrict__ dnn,
                                                       const float* __restrict__ gt,
                                                       float* __restrict__ out) {
    extern __shared__ float sm[];
    float*  sD  = sm;                               // [n = w*64 + h]
    float2* sCS = (float2*)(sm + 4096);             // [spatial*60 + freq]
    float2* sA  = (float2*)(sm + 4096 + 7680);      // [h*2 + pl] = (Ac, As)

    const int blk = blockIdx.x;
    const int b   = blk >> 4;                       // batch
    const int bt  = blk & 15;                       // row-pair tile: rows 2bt, 2bt+1
    const int t   = threadIdx.x;

    // ---- issue global loads FIRST (latency hidden by table gen below) ----
    const float4* d4 = (const float4*)(dnn + b * 4096);
    const float4* g4 = (const float4*)(gt  + b * 4096);
    float4 va[4], vg[4];
    #pragma unroll
    for (int k = 0; k < 4; k++) {                    // 4*256 = 1024 float4 = ALL of D
        va[k] = d4[t + k * NT];
        vg[k] = g4[t + k * NT];
    }

    // ---- full trig table, block-private, 15 entries/thread (R13-proven) ----
    // Ref: angle = fl(r_q * x_i) fp32, then cos/sin. Exact fp32 Cody-Waite:
    // kk = rint(a/2pi) (|kk|<=243 exact); fma(-kk, 6.28125f, a) EXACT (both
    // multiples of 2^-13, |diff|<=3.6); 2nd fma ~3e-7 rad; __sincosf ~5e-7.
    {
        const float inv2pi = 0.15915494309189535f;
        const float C1 = 6.28125f;                   // 201/32, exact
        const float C2 = 1.9353071795864769e-3f;     // 2*pi - C1
        int i = t / 60;
        int q = t - i * 60;
        #pragma unroll
        for (int k = 0; k < 15; k++) {
            float r  = (float)(q - 30) * 0.1f;       // fp32 grid, matches ref
            float x  = (float)(4 + 8 * i);           // linspace(4,508,64), exact
            float a  = r * x;                        // ref's fp32 angle
            float kk = rintf(a * inv2pi);
            float ar = fmaf(-kk, C1, a);             // exact
            ar       = fmaf(-kk, C2, ar);            // |ar| <= pi (+eps)
            float s, c;
            __sincosf(ar, &s, &c);
            sCS[i * 60 + q] = make_float2(c, s);
            q += 16; i += 4;
            if (q >= 60) { q -= 60; i += 1; }
        }
    }

    // ---- D = dnn - gt into shared ----
    {
        float4* sD4 = (float4*)sD;
        #pragma unroll
        for (int k = 0; k < 4; k++) {
            sD4[t + k * NT] = make_float4(va[k].x - vg[k].x, va[k].y - vg[k].y,
                                          va[k].z - vg[k].z, va[k].w - vg[k].w);
        }
    }
    __syncthreads();                                 // bar 1: sD + sCS ready

    // ---- stage 1: threads 0..127: A[p, h] = sum_w trig(r_p x_w) D[h, w] ----
    // t = pl*64 + h (pl uniform per 2 warps); p = 2bt + pl (<= 31).
    if (t < 128) {
        const int pl = t >> 6;
        const int h  = t & 63;
        const int p  = 2 * bt + pl;
        float ac = 0.f, as = 0.f;
        #pragma unroll 16
        for (int w = 0; w < 64; w++) {
            float  d  = sD[w * 64 + h];      // 32 consecutive -> 1 wf
            float2 cs = sCS[w * PP + p];     // broadcast (p uniform per warp)
            ac = fmaf(cs.x, d, ac);
            as = fmaf(cs.y, d, as);
        }
        sA[h * 2 + pl] = make_float2(ac, as);
    }
    __syncthreads();                                 // bar 2: sA ready

    // ---- stage 2: threads 0..121 ----
    // t<120: normal point (q = t>>1, pl = t&1), sg=+1.
    // t=120,121: conjugate point (60-row, 0): uses conj(A[row]) => sg=-1, q=0.
    float v = 0.f;
    if (t < 122) {
        const bool nrm = (t < 120);
        const int  q   = nrm ? (t >> 1) : 0;
        const int  pl  = nrm ? (t & 1)  : (t - 120);
        const float sg = nrm ? 1.f : -1.f;
        const int  row = 2 * bt + pl;
        float re1 = 0.f, re2 = 0.f, im1 = 0.f, im2 = 0.f;
        #pragma unroll 16
        for (int h = 0; h < 64; h++) {
            float2 a  = sA[h * 2 + pl];      // 2 distinct addrs -> 1 wf
            float2 cs = sCS[h * PP + q];     // 16 consecutive q x2 dup -> 1 wf
            re1 = fmaf(a.x, cs.x, re1);
            re2 = fmaf(a.y, cs.y, re2);
            im1 = fmaf(a.y, cs.x, im1);
            im2 = fmaf(a.x, cs.y, im2);
        }
        float re = fmaf(-sg, re2, re1);      // re1 - sg*re2
        float im = fmaf( sg, im1, im2);      // sg*im1 + im2
        float w;
        if (nrm) {
            // rows 1..29, q>=1: mirror-doubled; row 31 (bt=15,pl=1): weight 0
            w = (row >= 1 && row <= 29) ? ((q >= 1) ? 2.f : 1.f)
                                        : ((row <= 30) ? 1.f : 0.f);
        } else {
            // conj point (60-row, 0) valid only for rows 1..29
            w = (row >= 1 && row <= 29) ? 1.f : 0.f;
        }
        v = w * fmaf(re, re, im * im);
    }

    // ---- block reduce: warp shfl -> sD partials (sD free since bar 2) ----
    #pragma unroll
    for (int off = 16; off > 0; off >>= 1)
        v += __shfl_down_sync(0xFFFFFFFFu, v, off);
    if ((t & 31) == 0) sD[t >> 5] = v;               // 8 warp partials
    __syncthreads();                                 // bar 3
    if (t == 0) {
        float s = 0.f;
        #pragma unroll
        for (int w = 0; w < 8; w++) s += sD[w];
        g_part[b * 16 + bt] = s;
        __threadfence();                             // release before counter bump
        unsigned c = atomicAdd(&g_count, 1u);
        bool last = (c == NBLK - 1);
        if (last) g_count = 0;                       // reset for next graph replay
        sD[8] = last ? 1.f : 0.f;                    // flag in dynamic smem
    }
    __syncthreads();                                 // bar 4

    // ---- last block: deterministic finalize ----
    if (sD[8] != 0.f && t < 32) {
        __threadfence();                             // acquire: all g_part visible
        float w = 0.f;
        if (t < NB) {
            const float4* gp4 = (const float4*)(g_part + t * 16);
            float s = 0.f;
            #pragma unroll
            for (int k = 0; k < 4; k++) {            // fixed order -> deterministic
                float4 p = gp4[k];
                s += p.x + p.y + p.z + p.w;
            }
            w = sqrtf(s);
        }
        #pragma unroll
        for (int off = 4; off > 0; off >>= 1)        // 8-lane reduce
            w += __shfl_down_sync(0xFFFFFFFFu, w, off);
        if (t == 0) out[0] = w * 0.1f / 8.0f;
    }
}

// ---------------------------------------------------------------------------
extern "C" void kernel_launch(void* const* d_in, const int* in_sizes, int n_in,
                              void* d_out, int out_size) {
    (void)in_sizes; (void)n_in; (void)out_size;
    const float* dnn = (const float*)d_in[0];
    const float* gt  = (const float*)d_in[1];
    float* out = (float*)d_out;

    chf_fused_kernel<<<NBLK, NT, 12288 * sizeof(float)>>>(dnn, gt, out);
}

// round 16
// speedup vs baseline: 1.4963x; 1.0257x over previous
#include <cuda_runtime.h>
#include <math.h>

// ChfLoss: B=8, H=W=64, P=60. loss = (0.1/B) * sum_b ||CHF(dnn_b - gt_b)||_2
// Separable trig + conjugate symmetry (R15): compute p-rows 0..30 only,
// double rows 1..29 for q>=1, recover (60-p, 0) via conj(A[p]).
// R16: stage 2 in q-pair form (float4 trig loads, h-half split, warps 0..3),
// bar4 replaced by intra-warp shfl broadcast of the 'last' flag.

#define NB      8
#define HWD     64
#define PP      60
#define BPB     16                  // blocks per batch (rows 0..30, 2 per block)
#define NBLK    (NB * BPB)          // 128
#define NT      256

// __device__ globals = sanctioned scratch (no allocation allowed)
__device__ float    g_part[NB * 16];      // [b*16 + bt]
__device__ unsigned g_count = 0;          // completion counter (self-reset)

// Shared: D 4096 + CS 7680 + A 256 (+pad) = 12288 floats = 48KB dynamic.
// NO static __shared__ anywhere (would exceed the 48KB default limit).
__global__ __launch_bounds__(NT) void chf_fused_kernel(const float* __restrict__ dnn,
                                                       const float* __restrict__ gt,
                                                       float* __restrict__ out) {
    extern __shared__ float sm[];
    float*  sD  = sm;                               // [n = w*64 + h]
    float2* sCS = (float2*)(sm + 4096);             // [spatial*60 + freq]
    float2* sA  = (float2*)(sm + 4096 + 7680);      // [h*2 + pl] = (Ac, As)

    const int blk = blockIdx.x;
    const int b   = blk >> 4;                       // batch
    const int bt  = blk & 15;                       // row tile: rows 2bt, 2bt+1
    const int t   = threadIdx.x;

    // ---- issue global loads FIRST (latency hides the trig table gen) ----
    const float4* d4 = (const float4*)(dnn + b * 4096);
    const float4* g4 = (const float4*)(gt  + b * 4096);
    float4 va[4], vg[4];
    #pragma unroll
    for (int k = 0; k < 4; k++) {                    // 4*256 = 1024 float4 = ALL of D
        va[k] = d4[t + k * NT];
        vg[k] = g4[t + k * NT];
    }

    // ---- full trig table, block-private, 15 entries/thread (R13-proven) ----
    // Ref: angle = fl(r_q * x_i) fp32, then cos/sin. Exact fp32 Cody-Waite:
    // kk = rint(a/2pi) (|kk|<=243 exact); fma(-kk, 6.28125f, a) EXACT (both
    // multiples of 2^-13, |diff|<=3.6); 2nd fma ~3e-7 rad; __sincosf ~5e-7.
    {
        const float inv2pi = 0.15915494309189535f;
        const float C1 = 6.28125f;                   // 201/32, exact
        const float C2 = 1.9353071795864769e-3f;     // 2*pi - C1
        int i = t / 60;
        int q = t - i * 60;
        #pragma unroll
        for (int k = 0; k < 15; k++) {
            float r  = (float)(q - 30) * 0.1f;       // fp32 grid, matches ref
            float x  = (float)(4 + 8 * i);           // linspace(4,508,64), exact
            float a  = r * x;                        // ref's fp32 angle
            float kk = rintf(a * inv2pi);
            float ar = fmaf(-kk, C1, a);             // exact
            ar       = fmaf(-kk, C2, ar);            // |ar| <= pi (+eps)
            float s, c;
            __sincosf(ar, &s, &c);
            sCS[i * 60 + q] = make_float2(c, s);
            q += 16; i += 4;
            if (q >= 60) { q -= 60; i += 1; }
        }
    }

    // ---- D = dnn - gt into shared ----
    {
        float4* sD4 = (float4*)sD;
        #pragma unroll
        for (int k = 0; k < 4; k++) {
            sD4[t + k * NT] = make_float4(va[k].x - vg[k].x, va[k].y - vg[k].y,
                                          va[k].z - vg[k].z, va[k].w - vg[k].w);
        }
    }
    __syncthreads();                                 // bar 1: sD + sCS ready

    // ---- stage 1: threads 0..127: A[p, h] = sum_w trig(r_p x_w) D[h, w] ----
    if (t < 128) {
        const int pl = t >> 6;
        const int h  = t & 63;
        const int p  = 2 * bt + pl;
        float ac = 0.f, as = 0.f;
        #pragma unroll 16
        for (int w = 0; w < 64; w++) {
            float  d  = sD[w * 64 + h];      // 32 consecutive -> 1 wf
            float2 cs = sCS[w * PP + p];     // broadcast (p uniform per warp)
            ac = fmaf(cs.x, d, ac);
            as = fmaf(cs.y, d, as);
        }
        sA[h * 2 + pl] = make_float2(ac, as);
    }
    __syncthreads();                                 // bar 2: sA ready

    // ---- stage 2 (q-pair + h-half split, warps 0..3 only) ----
    // t<120: t = q2*4 + pl*2 + ih: q-pair (2q2, 2q2+1), row 2bt+pl, sg=+1.
    // t in [120,124): conj point (60-row, 0): sg=-1, q2=0, only q=0 weighted.
    // t in [124,128): dead lanes (weights 0), run loop with clamped q2.
    float v = 0.f;
    if (t < 128) {
        const int  ih  = t & 1;                      // h half
        const int  pl  = (t >> 1) & 1;
        const int  q2r = t >> 2;                     // 0..31
        const bool nrm = (t < 120);
        const int  q2  = nrm ? q2r : 0;              // conj/dead use q2=0 (in-bounds)
        const float sg = nrm ? 1.f : -1.f;
        const int  row = 2 * bt + pl;
        const int  h0  = ih * 32;
        float r0a = 0.f, r0b = 0.f, i0a = 0.f, i0b = 0.f;
        float r1a = 0.f, r1b = 0.f, i1a = 0.f, i1b = 0.f;
        const float4* sCS4 = (const float4*)sCS;     // [h*30 + q2] = q pair
        #pragma unroll 16
        for (int hh = 0; hh < 32; hh++) {
            int h = h0 + hh;
            float2 a  = sA[h * 2 + pl];              // (Ac, As)
            float4 cs = sCS4[h * 30 + q2];           // (c_q0,s_q0,c_q1,s_q1)
            r0a = fmaf(a.x, cs.x, r0a);
            r0b = fmaf(a.y, cs.y, r0b);
            i0a = fmaf(a.y, cs.x, i0a);
            i0b = fmaf(a.x, cs.y, i0b);
            r1a = fmaf(a.x, cs.z, r1a);
            r1b = fmaf(a.y, cs.w, r1b);
            i1a = fmaf(a.y, cs.z, i1a);
            i1b = fmaf(a.x, cs.w, i1b);
        }
        float re0 = fmaf(-sg, r0b, r0a);             // re1 - sg*re2
        float im0 = fmaf( sg, i0a, i0b);             // sg*im1 + im2
        float re1 = fmaf(-sg, r1b, r1a);
        float im1 = fmaf( sg, i1a, i1b);
        // combine h halves with partner lane (t^1): exact & deterministic
        re0 += __shfl_xor_sync(0xFFFFFFFFu, re0, 1);
        im0 += __shfl_xor_sync(0xFFFFFFFFu, im0, 1);
        re1 += __shfl_xor_sync(0xFFFFFFFFu, re1, 1);
        im1 += __shfl_xor_sync(0xFFFFFFFFu, im1, 1);
        if (!ih) {
            float w0, w1;
            if (nrm) {
                // row 31 -> 0; rows 1..29: q>=1 doubled; rows 0,30: 1
                bool mid = (row >= 1 && row <= 29);
                float base = (row <= 30) ? 1.f : 0.f;
                w0 = mid ? ((q2 >= 1) ? 2.f : 1.f) : base;   // q0 = 2q2
                w1 = mid ? 2.f : base;                       // q1 = 2q2+1 >= 1
            } else {
                w0 = (t < 124 && row >= 1 && row <= 29) ? 1.f : 0.f;
                w1 = 0.f;
            }
            v = w0 * fmaf(re0, re0, im0 * im0)
              + w1 * fmaf(re1, re1, im1 * im1);
        }
        // warp reduce (warps 0..3 hold all nonzero v)
        #pragma unroll
        for (int off = 16; off > 0; off >>= 1)
            v += __shfl_down_sync(0xFFFFFFFFu, v, off);
        if ((t & 31) == 0) sD[t >> 5] = v;           // 4 warp partials
    }
    __syncthreads();                                 // bar 3 (last barrier)

    // ---- tail: t0 publishes partial; warp 0 finalizes if last (no bar4) ----
    if (t < 32) {
        int last = 0;
        if (t == 0) {
            float s = (sD[0] + sD[1]) + (sD[2] + sD[3]);
            g_part[b * 16 + bt] = s;
            __threadfence();                         // release before counter bump
            unsigned c = atomicAdd(&g_count, 1u);
            last = (c == NBLK - 1) ? 1 : 0;
            if (last) g_count = 0;                   // reset for next graph replay
        }
        last = __shfl_sync(0xFFFFFFFFu, last, 0);    // warp-0 broadcast
        if (last) {
            __threadfence();                         // acquire: all g_part visible
            float w = 0.f;
            if (t < NB) {
                const float4* gp4 = (const float4*)(g_part + t * 16);
                float s = 0.f;
                #pragma unroll
                for (int k = 0; k < 4; k++) {        // fixed order -> deterministic
                    float4 p = gp4[k];
                    s += p.x + p.y + p.z + p.w;
                }
                w = sqrtf(s);
            }
            #pragma unroll
            for (int off = 4; off > 0; off >>= 1)    // 8-lane reduce
                w += __shfl_down_sync(0xFFFFFFFFu, w, off);
            if (t == 0) out[0] = w * 0.1f / 8.0f;
        }
    }
}

// ---------------------------------------------------------------------------
extern "C" void kernel_launch(void* const* d_in, const int* in_sizes, int n_in,
                              void* d_out, int out_size) {
    (void)in_sizes; (void)n_in; (void)out_size;
    const float* dnn = (const float*)d_in[0];
    const float* gt  = (const float*)d_in[1];
    float* out = (float*)d_out;

    chf_fused_kernel<<<NBLK, NT, 12288 * sizeof(float)>>>(dnn, gt, out);
}